// round 10
// baseline (speedup 1.0000x reference)
#include <cuda_runtime.h>
#include <cuda_bf16.h>
#include <cstdint>

// ---------------- problem constants ----------------
#define BB 8
#define SS 8192
#define DD 512
#define HH 512
#define OO 512
#define MM (BB*SS)        // 65536 rows
#define CHUNKS 64
#define CLEN (SS/CHUNKS)  // 128

// ---------------- scratch (no allocs allowed) ----------------
__device__ float           g_a[MM*HH];        // coeff  c = sigmoid(-gate)
__device__ float           g_b[MM*HH];        // value  v = sigmoid(gate)*G(hidden)
__device__ __nv_bfloat16   g_xh[MM*DD];       // x split hi
__device__ __nv_bfloat16   g_xl[MM*DD];       // x split lo
__device__ __nv_bfloat16   g_hh[MM*HH];       // h split hi
__device__ __nv_bfloat16   g_hl[MM*HH];       // h split lo
__device__ __nv_bfloat16   g_whg_h[2*HH*DD], g_whg_l[2*HH*DD];
__device__ __nv_bfloat16   g_wout_h[OO*HH],  g_wout_l[OO*HH];
__device__ float           g_Ac[BB*CHUNKS*HH];
__device__ float           g_Bc[BB*CHUNKS*HH];
__device__ float           g_H0[BB*CHUNKS*HH];
__device__ float           g_hn[BB*HH];       // exact fp32 last-step h

// ---------------- mma helper (legacy path — compiles at compute_103) ----
__device__ __forceinline__ void mma_bf16(float& d0, float& d1, float& d2, float& d3,
                                         unsigned a0, unsigned a1, unsigned a2, unsigned a3,
                                         unsigned b0, unsigned b1)
{
    asm volatile(
        "mma.sync.aligned.m16n8k16.row.col.f32.bf16.bf16.f32 "
        "{%0,%1,%2,%3}, {%4,%5,%6,%7}, {%8,%9}, {%0,%1,%2,%3};\n"
        : "+f"(d0), "+f"(d1), "+f"(d2), "+f"(d3)
        : "r"(a0), "r"(a1), "r"(a2), "r"(a3), "r"(b0), "r"(b1));
}

// Tiling (both GEMMs): 256 threads (8 warps), tile 128(M) x 64(N), BK=16.
// Warp grid 4(m) x 2(n), warp tile 32x32 -> MF=2, NF=4.  SPAD in bf16 elems.
#define BK 16
#define SPAD 24     // 48B row stride: words g*12+tg all distinct mod 32 -> conflict-free

// =====================================================================
// split: fp32 -> bf16 hi/lo
// =====================================================================
__device__ __forceinline__ void split4_store(const float4 v, unsigned* hi, unsigned* lo, long long i2)
{
    __nv_bfloat16 xh=__float2bfloat16(v.x), yh=__float2bfloat16(v.y);
    __nv_bfloat16 zh=__float2bfloat16(v.z), wh=__float2bfloat16(v.w);
    __nv_bfloat16 xl=__float2bfloat16(v.x-__bfloat162float(xh));
    __nv_bfloat16 yl=__float2bfloat16(v.y-__bfloat162float(yh));
    __nv_bfloat16 zl=__float2bfloat16(v.z-__bfloat162float(zh));
    __nv_bfloat16 wl=__float2bfloat16(v.w-__bfloat162float(wh));
    __nv_bfloat162 a=__halves2bfloat162(xh,yh), b=__halves2bfloat162(zh,wh);
    __nv_bfloat162 c=__halves2bfloat162(xl,yl), d=__halves2bfloat162(zl,wl);
    hi[i2]   = *(unsigned*)&a;  hi[i2+1] = *(unsigned*)&b;
    lo[i2]   = *(unsigned*)&c;  lo[i2+1] = *(unsigned*)&d;
}
__global__ __launch_bounds__(256) void split_x(const float4* __restrict__ in)
{
    long long i = (long long)blockIdx.x*256 + threadIdx.x;
    split4_store(in[i], (unsigned*)g_xh, (unsigned*)g_xl, 2*i);
}
__global__ __launch_bounds__(256) void split_whg(const float4* __restrict__ in)
{
    long long i = (long long)blockIdx.x*256 + threadIdx.x;
    split4_store(in[i], (unsigned*)g_whg_h, (unsigned*)g_whg_l, 2*i);
}
__global__ __launch_bounds__(256) void split_wout(const float4* __restrict__ in)
{
    long long i = (long long)blockIdx.x*256 + threadIdx.x;
    split4_store(in[i], (unsigned*)g_wout_h, (unsigned*)g_wout_l, 2*i);
}

// =====================================================================
// GEMM1: hg = x @ W_hg^T (bf16-split HMMA, pre-split inputs), fused act.
// CTA: 128 rows x 64 interleaved cols (32 h).  grid = (16, 512)
// =====================================================================
__global__ __launch_bounds__(256, 2) void gemm1_mma()
{
    __shared__ __align__(16) unsigned short Ah[128][SPAD], Al[128][SPAD];
    __shared__ __align__(16) unsigned short Bh[64][SPAD],  Bl[64][SPAD];

    const int tid = threadIdx.x;
    const int m0  = blockIdx.y * 128;
    const int hb  = blockIdx.x * 32;          // h-column base

    const int lane = tid & 31;
    const int wid  = tid >> 5;
    const int wm   = wid & 3;
    const int wn   = wid >> 2;
    const int g    = lane >> 2;
    const int tg   = lane & 3;

    // staging: A 128 rows x 16 bf16 = 2 uint4/row -> 1 uint4/thread (hi & lo)
    //          B 64 rows            -> threads < 128
    const int arow = tid >> 1, ahalf = tid & 1;
    const int brow = (tid & 127) >> 1, bhalf = tid & 1;
    const int be   = (brow & 1) ? (HH + hb + (brow >> 1)) : (hb + (brow >> 1));

    const uint4* XH = (const uint4*)g_xh;
    const uint4* XL = (const uint4*)g_xl;
    const uint4* WH = (const uint4*)g_whg_h;
    const uint4* WL = (const uint4*)g_whg_l;

    uint4 pah, pal, pbh, pbl;
    auto ldg = [&](int kt) {
        long long ai = ((long long)(m0 + arow)*DD + kt*BK + ahalf*8) >> 3;
        pah = XH[ai];  pal = XL[ai];
        if (tid < 128) {
            long long bi = ((long long)be*DD + kt*BK + bhalf*8) >> 3;
            pbh = WH[bi];  pbl = WL[bi];
        }
    };
    auto stg = [&]() {
        *(uint4*)&Ah[arow][ahalf*8] = pah;
        *(uint4*)&Al[arow][ahalf*8] = pal;
        if (tid < 128) {
            *(uint4*)&Bh[brow][bhalf*8] = pbh;
            *(uint4*)&Bl[brow][bhalf*8] = pbl;
        }
    };

    float acc[2][4][4];
    #pragma unroll
    for (int i = 0; i < 2; ++i)
        #pragma unroll
        for (int j = 0; j < 4; ++j)
            #pragma unroll
            for (int q = 0; q < 4; ++q) acc[i][j][q] = 0.f;

    ldg(0);
    const int KT = DD / BK;   // 32
    for (int kt = 0; kt < KT; ++kt) {
        stg();
        __syncthreads();
        if (kt + 1 < KT) ldg(kt + 1);

        unsigned ah[2][4], al[2][4], bh[4][2], bl[4][2];
        #pragma unroll
        for (int fm = 0; fm < 2; ++fm) {
            int r = wm*32 + fm*16 + g;
            ah[fm][0] = *(const unsigned*)&Ah[r  ][2*tg];
            ah[fm][1] = *(const unsigned*)&Ah[r+8][2*tg];
            ah[fm][2] = *(const unsigned*)&Ah[r  ][2*tg+8];
            ah[fm][3] = *(const unsigned*)&Ah[r+8][2*tg+8];
            al[fm][0] = *(const unsigned*)&Al[r  ][2*tg];
            al[fm][1] = *(const unsigned*)&Al[r+8][2*tg];
            al[fm][2] = *(const unsigned*)&Al[r  ][2*tg+8];
            al[fm][3] = *(const unsigned*)&Al[r+8][2*tg+8];
        }
        #pragma unroll
        for (int nf = 0; nf < 4; ++nf) {
            int c = wn*32 + nf*8 + g;
            bh[nf][0] = *(const unsigned*)&Bh[c][2*tg];
            bh[nf][1] = *(const unsigned*)&Bh[c][2*tg+8];
            bl[nf][0] = *(const unsigned*)&Bl[c][2*tg];
            bl[nf][1] = *(const unsigned*)&Bl[c][2*tg+8];
        }
        #pragma unroll
        for (int fm = 0; fm < 2; ++fm)
            #pragma unroll
            for (int nf = 0; nf < 4; ++nf) {
                float* d = acc[fm][nf];
                mma_bf16(d[0],d[1],d[2],d[3], ah[fm][0],ah[fm][1],ah[fm][2],ah[fm][3], bh[nf][0],bh[nf][1]);
                mma_bf16(d[0],d[1],d[2],d[3], ah[fm][0],ah[fm][1],ah[fm][2],ah[fm][3], bl[nf][0],bl[nf][1]);
                mma_bf16(d[0],d[1],d[2],d[3], al[fm][0],al[fm][1],al[fm][2],al[fm][3], bh[nf][0],bh[nf][1]);
            }
        __syncthreads();
    }

    // activation epilogue: (c0,c1) = (hidden,gate) at row r; (c2,c3) at row r+8
    #pragma unroll
    for (int fm = 0; fm < 2; ++fm) {
        #pragma unroll
        for (int nf = 0; nf < 4; ++nf) {
            int hcol = hb + wn*16 + nf*4 + tg;
            int r0 = m0 + wm*32 + fm*16 + g;
            #pragma unroll
            for (int half = 0; half < 2; ++half) {
                int m  = r0 + half*8;
                float hid = acc[fm][nf][2*half];
                float gat = acc[fm][nf][2*half+1];
                float eg = __expf(gat);
                float cc = 1.f / (1.f + eg);          // sigmoid(-gate)
                float sg = 1.f - cc;                  // sigmoid(gate)
                float G  = (hid >= 0.f) ? (hid + 0.5f)
                                        : (1.f / (1.f + __expf(-hid)));
                g_a[(long long)m*HH + hcol] = cc;
                g_b[(long long)m*HH + hcol] = sg * G;
            }
        }
    }
}

// =====================================================================
// Scan phase 1: per (b, chunk) carry (A,B), float2-vectorized
// =====================================================================
__global__ __launch_bounds__(256) void scan_phase1()
{
    int c = blockIdx.x, b = blockIdx.z, t = threadIdx.x;
    long long base2 = ((long long)(b*SS + c*CLEN)*HH) >> 1;
    const float2* ap = (const float2*)g_a + base2 + t;
    const float2* bp = (const float2*)g_b + base2 + t;
    float Ax = 1.f, Ay = 1.f, Bx = 0.f, By = 0.f;
    #pragma unroll 8
    for (int s = 0; s < CLEN; ++s) {
        float2 a = ap[(long long)s*(HH/2)];
        float2 v = bp[(long long)s*(HH/2)];
        Bx = a.x*Bx + v.x;  By = a.y*By + v.y;
        Ax *= a.x;          Ay *= a.y;
    }
    int ci = (b*CHUNKS + c)*HH + 2*t;
    *(float2*)&g_Ac[ci] = make_float2(Ax, Ay);
    *(float2*)&g_Bc[ci] = make_float2(Bx, By);
}

// =====================================================================
// Scan phase 2: sequential over chunks per channel
// =====================================================================
__global__ __launch_bounds__(256) void scan_phase2()
{
    int t = blockIdx.x*256 + threadIdx.x;     // 0..4095
    int b = t >> 9, hh = t & 511;
    float run = 0.f;
    for (int c = 0; c < CHUNKS; ++c) {
        int ci = (b*CHUNKS + c)*HH + hh;
        g_H0[ci] = run;
        run = g_Ac[ci]*run + g_Bc[ci];
    }
}

// =====================================================================
// Scan phase 3: recurrence within chunk -> bf16 hi/lo h; exact fp32 h_n
// =====================================================================
__global__ __launch_bounds__(256) void scan_phase3()
{
    int c = blockIdx.x, b = blockIdx.z, t = threadIdx.x;
    long long base2 = ((long long)(b*SS + c*CLEN)*HH) >> 1;
    const float2* ap = (const float2*)g_a + base2 + t;
    const float2* bp = (const float2*)g_b + base2 + t;
    unsigned* hhp = (unsigned*)g_hh + base2 + t;
    unsigned* hlp = (unsigned*)g_hl + base2 + t;
    int ci = (b*CHUNKS + c)*HH + 2*t;
    float h0 = g_H0[ci], h1 = g_H0[ci+1];
    #pragma unroll 8
    for (int s = 0; s < CLEN; ++s) {
        float2 a = ap[(long long)s*(HH/2)];
        float2 v = bp[(long long)s*(HH/2)];
        h0 = a.x*h0 + v.x;
        h1 = a.y*h1 + v.y;
        __nv_bfloat16 h0h = __float2bfloat16(h0), h1h = __float2bfloat16(h1);
        __nv_bfloat16 h0l = __float2bfloat16(h0 - __bfloat162float(h0h));
        __nv_bfloat16 h1l = __float2bfloat16(h1 - __bfloat162float(h1h));
        __nv_bfloat162 ph = __halves2bfloat162(h0h, h1h);
        __nv_bfloat162 pl = __halves2bfloat162(h0l, h1l);
        hhp[(long long)s*(HH/2)] = *(unsigned*)&ph;
        hlp[(long long)s*(HH/2)] = *(unsigned*)&pl;
    }
    if (c == CHUNKS-1) {
        g_hn[b*HH + 2*t]   = h0;
        g_hn[b*HH + 2*t+1] = h1;
    }
}

// =====================================================================
// GEMM2: out = h @ W_out^T (bf16-split HMMA, pre-split inputs)
// grid = (8, 512); n0 = bx*64
// =====================================================================
__global__ __launch_bounds__(256, 2) void gemm2_mma(float* __restrict__ out)
{
    __shared__ __align__(16) unsigned short Ah[128][SPAD], Al[128][SPAD];
    __shared__ __align__(16) unsigned short Bh[64][SPAD],  Bl[64][SPAD];

    const int tid = threadIdx.x;
    const int m0  = blockIdx.y * 128;
    const int n0  = blockIdx.x * 64;

    const int lane = tid & 31;
    const int wid  = tid >> 5;
    const int wm   = wid & 3;
    const int wn   = wid >> 2;
    const int g    = lane >> 2;
    const int tg   = lane & 3;

    const int arow = tid >> 1, ahalf = tid & 1;
    const int brow = (tid & 127) >> 1, bhalf = tid & 1;

    const uint4* AHp = (const uint4*)g_hh;
    const uint4* ALp = (const uint4*)g_hl;
    const uint4* WH  = (const uint4*)g_wout_h;
    const uint4* WL  = (const uint4*)g_wout_l;

    uint4 pah, pal, pbh, pbl;
    auto ldg = [&](int kt) {
        long long ai = ((long long)(m0 + arow)*HH + kt*BK + ahalf*8) >> 3;
        pah = AHp[ai];  pal = ALp[ai];
        if (tid < 128) {
            long long bi = ((long long)(n0 + brow)*HH + kt*BK + bhalf*8) >> 3;
            pbh = WH[bi];  pbl = WL[bi];
        }
    };
    auto stg = [&]() {
        *(uint4*)&Ah[arow][ahalf*8] = pah;
        *(uint4*)&Al[arow][ahalf*8] = pal;
        if (tid < 128) {
            *(uint4*)&Bh[brow][bhalf*8] = pbh;
            *(uint4*)&Bl[brow][bhalf*8] = pbl;
        }
    };

    float acc[2][4][4];
    #pragma unroll
    for (int i = 0; i < 2; ++i)
        #pragma unroll
        for (int j = 0; j < 4; ++j)
            #pragma unroll
            for (int q = 0; q < 4; ++q) acc[i][j][q] = 0.f;

    ldg(0);
    const int KT = HH / BK;   // 32
    for (int kt = 0; kt < KT; ++kt) {
        stg();
        __syncthreads();
        if (kt + 1 < KT) ldg(kt + 1);

        unsigned ah[2][4], al[2][4], bh[4][2], bl[4][2];
        #pragma unroll
        for (int fm = 0; fm < 2; ++fm) {
            int r = wm*32 + fm*16 + g;
            ah[fm][0] = *(const unsigned*)&Ah[r  ][2*tg];
            ah[fm][1] = *(const unsigned*)&Ah[r+8][2*tg];
            ah[fm][2] = *(const unsigned*)&Ah[r  ][2*tg+8];
            ah[fm][3] = *(const unsigned*)&Ah[r+8][2*tg+8];
            al[fm][0] = *(const unsigned*)&Al[r  ][2*tg];
            al[fm][1] = *(const unsigned*)&Al[r+8][2*tg];
            al[fm][2] = *(const unsigned*)&Al[r  ][2*tg+8];
            al[fm][3] = *(const unsigned*)&Al[r+8][2*tg+8];
        }
        #pragma unroll
        for (int nf = 0; nf < 4; ++nf) {
            int c = wn*32 + nf*8 + g;
            bh[nf][0] = *(const unsigned*)&Bh[c][2*tg];
            bh[nf][1] = *(const unsigned*)&Bh[c][2*tg+8];
            bl[nf][0] = *(const unsigned*)&Bl[c][2*tg];
            bl[nf][1] = *(const unsigned*)&Bl[c][2*tg+8];
        }
        #pragma unroll
        for (int fm = 0; fm < 2; ++fm)
            #pragma unroll
            for (int nf = 0; nf < 4; ++nf) {
                float* d = acc[fm][nf];
                mma_bf16(d[0],d[1],d[2],d[3], ah[fm][0],ah[fm][1],ah[fm][2],ah[fm][3], bh[nf][0],bh[nf][1]);
                mma_bf16(d[0],d[1],d[2],d[3], ah[fm][0],ah[fm][1],ah[fm][2],ah[fm][3], bl[nf][0],bl[nf][1]);
                mma_bf16(d[0],d[1],d[2],d[3], al[fm][0],al[fm][1],al[fm][2],al[fm][3], bh[nf][0],bh[nf][1]);
            }
        __syncthreads();
    }

    #pragma unroll
    for (int fm = 0; fm < 2; ++fm) {
        #pragma unroll
        for (int nf = 0; nf < 4; ++nf) {
            int cc = n0 + wn*32 + nf*8 + 2*tg;
            int r0 = m0 + wm*32 + fm*16 + g;
            float2 v0 = make_float2(acc[fm][nf][0], acc[fm][nf][1]);
            float2 v1 = make_float2(acc[fm][nf][2], acc[fm][nf][3]);
            *(float2*)&out[(long long)r0*OO + cc]       = v0;
            *(float2*)&out[(long long)(r0+8)*OO + cc]   = v1;
        }
    }
}

// =====================================================================
// h_n copy: exact fp32 last-step h -> tail of output buffer
// =====================================================================
__global__ void copy_hn(float* __restrict__ out)
{
    int t = blockIdx.x*256 + threadIdx.x;     // 0..4095
    out[(long long)MM*OO + t] = g_hn[t];
}

// =====================================================================
// launch
// =====================================================================
extern "C" void kernel_launch(void* const* d_in, const int* in_sizes, int n_in,
                              void* d_out, int out_size)
{
    const float* x    = (const float*)d_in[0];
    // d_in[1] = is_init : unused by the reference (all false)
    const float* Whg  = (const float*)d_in[2];
    const float* Wout = (const float*)d_in[3];
    float* out = (float*)d_out;

    split_x   <<<(MM*DD/4)/256,   256>>>((const float4*)x);
    split_whg <<<(2*HH*DD/4)/256, 256>>>((const float4*)Whg);
    split_wout<<<(OO*HH/4)/256,   256>>>((const float4*)Wout);

    gemm1_mma<<<dim3(16, MM/128), 256>>>();
    scan_phase1<<<dim3(CHUNKS, 1, BB), 256>>>();
    scan_phase2<<<16, 256>>>();
    scan_phase3<<<dim3(CHUNKS, 1, BB), 256>>>();
    gemm2_mma<<<dim3(8, MM/128), 256>>>(out);

    long long need = (long long)MM*OO + (long long)BB*HH;
    if ((long long)out_size >= need)
        copy_hn<<<16, 256>>>(out);
}

// round 14
// speedup vs baseline: 1.0983x; 1.0983x over previous
#include <cuda_runtime.h>
#include <cuda_bf16.h>
#include <cstdint>

// ---------------- problem constants ----------------
#define BB 8
#define SS 8192
#define DD 512
#define HH 512
#define OO 512
#define MM (BB*SS)        // 65536 rows
#define CHUNKS 64
#define CLEN (SS/CHUNKS)  // 128

// ---------------- scratch (no allocs allowed) ----------------
__device__ float           g_a[MM*HH];        // coeff  c = sigmoid(-gate)
__device__ float           g_b[MM*HH];        // value  v = sigmoid(gate)*G(hidden)
__device__ __nv_bfloat16   g_xh[MM*DD];       // x split hi
__device__ __nv_bfloat16   g_xl[MM*DD];       // x split lo
__device__ __nv_bfloat16   g_hh[MM*HH];       // h split hi
__device__ __nv_bfloat16   g_hl[MM*HH];       // h split lo
__device__ __nv_bfloat16   g_whg_h[2*HH*DD], g_whg_l[2*HH*DD];
__device__ __nv_bfloat16   g_wout_h[OO*HH],  g_wout_l[OO*HH];
__device__ float           g_Ac[BB*CHUNKS*HH];
__device__ float           g_Bc[BB*CHUNKS*HH];
__device__ float           g_H0[BB*CHUNKS*HH];
__device__ float           g_hn[BB*HH];       // exact fp32 last-step h

// ---------------- mma / ldmatrix helpers (legacy path, compute_103-safe) ----
__device__ __forceinline__ void mma_bf16(float& d0, float& d1, float& d2, float& d3,
                                         unsigned a0, unsigned a1, unsigned a2, unsigned a3,
                                         unsigned b0, unsigned b1)
{
    asm volatile(
        "mma.sync.aligned.m16n8k16.row.col.f32.bf16.bf16.f32 "
        "{%0,%1,%2,%3}, {%4,%5,%6,%7}, {%8,%9}, {%0,%1,%2,%3};\n"
        : "+f"(d0), "+f"(d1), "+f"(d2), "+f"(d3)
        : "r"(a0), "r"(a1), "r"(a2), "r"(a3), "r"(b0), "r"(b1));
}
__device__ __forceinline__ void ldsm4(unsigned* r, const void* p)
{
    uint32_t a = (uint32_t)__cvta_generic_to_shared(p);
    asm volatile("ldmatrix.sync.aligned.m8n8.x4.shared.b16 {%0,%1,%2,%3}, [%4];"
        : "=r"(r[0]), "=r"(r[1]), "=r"(r[2]), "=r"(r[3]) : "r"(a));
}

// Tiling (both GEMMs): 256 threads (8 warps), tile 128(M) x 64(N), BK=16.
// Warp grid 4(m) x 2(n), warp tile 32x32 -> MF=2, NF=4.  SPAD in bf16 elems.
#define BK 16
#define SPAD 24     // 48B row stride: ldmatrix phases & scalar loads conflict-free

// =====================================================================
// split: fp32 -> bf16 hi/lo
// =====================================================================
__device__ __forceinline__ void split4_store(const float4 v, unsigned* hi, unsigned* lo, long long i2)
{
    __nv_bfloat16 xh=__float2bfloat16(v.x), yh=__float2bfloat16(v.y);
    __nv_bfloat16 zh=__float2bfloat16(v.z), wh=__float2bfloat16(v.w);
    __nv_bfloat16 xl=__float2bfloat16(v.x-__bfloat162float(xh));
    __nv_bfloat16 yl=__float2bfloat16(v.y-__bfloat162float(yh));
    __nv_bfloat16 zl=__float2bfloat16(v.z-__bfloat162float(zh));
    __nv_bfloat16 wl=__float2bfloat16(v.w-__bfloat162float(wh));
    __nv_bfloat162 a=__halves2bfloat162(xh,yh), b=__halves2bfloat162(zh,wh);
    __nv_bfloat162 c=__halves2bfloat162(xl,yl), d=__halves2bfloat162(zl,wl);
    hi[i2]   = *(unsigned*)&a;  hi[i2+1] = *(unsigned*)&b;
    lo[i2]   = *(unsigned*)&c;  lo[i2+1] = *(unsigned*)&d;
}
__global__ __launch_bounds__(256) void split_x(const float4* __restrict__ in)
{
    long long i = (long long)blockIdx.x*256 + threadIdx.x;
    split4_store(in[i], (unsigned*)g_xh, (unsigned*)g_xl, 2*i);
}
__global__ __launch_bounds__(256) void split_whg(const float4* __restrict__ in)
{
    long long i = (long long)blockIdx.x*256 + threadIdx.x;
    split4_store(in[i], (unsigned*)g_whg_h, (unsigned*)g_whg_l, 2*i);
}
__global__ __launch_bounds__(256) void split_wout(const float4* __restrict__ in)
{
    long long i = (long long)blockIdx.x*256 + threadIdx.x;
    split4_store(in[i], (unsigned*)g_wout_h, (unsigned*)g_wout_l, 2*i);
}

// =====================================================================
// GEMM1: hg = x @ W_hg^T (bf16-split HMMA + ldmatrix + dbl-buffer), fused act.
// CTA: 128 rows x 64 interleaved cols (32 h).  grid = (16, 512)
// =====================================================================
__global__ __launch_bounds__(256, 2) void gemm1_mma()
{
    __shared__ __align__(16) unsigned short Ah[2][128][SPAD], Al[2][128][SPAD];
    __shared__ __align__(16) unsigned short Bh[2][64][SPAD],  Bl[2][64][SPAD];

    const int tid = threadIdx.x;
    const int m0  = blockIdx.y * 128;
    const int hb  = blockIdx.x * 32;          // h-column base

    const int lane = tid & 31;
    const int wid  = tid >> 5;
    const int wm   = wid & 3;
    const int wn   = wid >> 2;
    const int g    = lane >> 2;
    const int tg   = lane & 3;

    // ldmatrix per-lane row/col selectors
    const int m4    = lane >> 3;
    const int arowf = (lane & 7) + (m4 & 1)*8;   // A: rows 0..15 within 16-row frag
    const int akcol = (m4 >> 1)*8;               // A: k-halves 0 or 8
    const int bcolf = (lane & 7) + (m4 >> 1)*8;  // B: cols 0..15 within 16-col pair
    const int bkcol = (m4 & 1)*8;                // B: k-halves 0 or 8

    // staging: A 128 rows x 16 bf16 -> 1 uint4/thread (hi & lo); B 64 rows -> tid<128
    const int arow = tid >> 1, ahalf = tid & 1;
    const int brow = (tid & 127) >> 1, bhalf = tid & 1;
    const int be   = (brow & 1) ? (HH + hb + (brow >> 1)) : (hb + (brow >> 1));

    const uint4* XH = (const uint4*)g_xh;
    const uint4* XL = (const uint4*)g_xl;
    const uint4* WH = (const uint4*)g_whg_h;
    const uint4* WL = (const uint4*)g_whg_l;

    uint4 pah, pal, pbh, pbl;
    auto ldg = [&](int kt) {
        long long ai = ((long long)(m0 + arow)*DD + kt*BK + ahalf*8) >> 3;
        pah = XH[ai];  pal = XL[ai];
        if (tid < 128) {
            long long bi = ((long long)be*DD + kt*BK + bhalf*8) >> 3;
            pbh = WH[bi];  pbl = WL[bi];
        }
    };
    auto stg = [&](int buf) {
        *(uint4*)&Ah[buf][arow][ahalf*8] = pah;
        *(uint4*)&Al[buf][arow][ahalf*8] = pal;
        if (tid < 128) {
            *(uint4*)&Bh[buf][brow][bhalf*8] = pbh;
            *(uint4*)&Bl[buf][brow][bhalf*8] = pbl;
        }
    };

    float acc[2][4][4];
    #pragma unroll
    for (int i = 0; i < 2; ++i)
        #pragma unroll
        for (int j = 0; j < 4; ++j)
            #pragma unroll
            for (int q = 0; q < 4; ++q) acc[i][j][q] = 0.f;

    ldg(0); stg(0);
    __syncthreads();

    const int KT = DD / BK;   // 32
    #pragma unroll 2
    for (int kt = 0; kt < KT; ++kt) {
        const int buf = kt & 1;
        if (kt + 1 < KT) ldg(kt + 1);

        unsigned ah[2][4], al[2][4], bh[4][2], bl[4][2], t[4];
        #pragma unroll
        for (int fm = 0; fm < 2; ++fm) {
            ldsm4(ah[fm], &Ah[buf][wm*32 + fm*16 + arowf][akcol]);
            ldsm4(al[fm], &Al[buf][wm*32 + fm*16 + arowf][akcol]);
        }
        #pragma unroll
        for (int pr = 0; pr < 2; ++pr) {
            ldsm4(t, &Bh[buf][wn*32 + pr*16 + bcolf][bkcol]);
            bh[2*pr][0]=t[0]; bh[2*pr][1]=t[1]; bh[2*pr+1][0]=t[2]; bh[2*pr+1][1]=t[3];
            ldsm4(t, &Bl[buf][wn*32 + pr*16 + bcolf][bkcol]);
            bl[2*pr][0]=t[0]; bl[2*pr][1]=t[1]; bl[2*pr+1][0]=t[2]; bl[2*pr+1][1]=t[3];
        }

        #pragma unroll
        for (int fm = 0; fm < 2; ++fm)
            #pragma unroll
            for (int nf = 0; nf < 4; ++nf) {
                float* d = acc[fm][nf];
                mma_bf16(d[0],d[1],d[2],d[3], ah[fm][0],ah[fm][1],ah[fm][2],ah[fm][3], bh[nf][0],bh[nf][1]);
                mma_bf16(d[0],d[1],d[2],d[3], ah[fm][0],ah[fm][1],ah[fm][2],ah[fm][3], bl[nf][0],bl[nf][1]);
                mma_bf16(d[0],d[1],d[2],d[3], al[fm][0],al[fm][1],al[fm][2],al[fm][3], bh[nf][0],bh[nf][1]);
            }

        if (kt + 1 < KT) stg(buf ^ 1);
        __syncthreads();
    }

    // activation epilogue: (c0,c1) = (hidden,gate) at row r; (c2,c3) at row r+8
    #pragma unroll
    for (int fm = 0; fm < 2; ++fm) {
        #pragma unroll
        for (int nf = 0; nf < 4; ++nf) {
            int hcol = hb + wn*16 + nf*4 + tg;
            int r0 = m0 + wm*32 + fm*16 + g;
            #pragma unroll
            for (int half = 0; half < 2; ++half) {
                int m  = r0 + half*8;
                float hid = acc[fm][nf][2*half];
                float gat = acc[fm][nf][2*half+1];
                float eg = __expf(gat);
                float cc = 1.f / (1.f + eg);          // sigmoid(-gate)
                float sg = 1.f - cc;                  // sigmoid(gate)
                float G  = (hid >= 0.f) ? (hid + 0.5f)
                                        : (1.f / (1.f + __expf(-hid)));
                g_a[(long long)m*HH + hcol] = cc;
                g_b[(long long)m*HH + hcol] = sg * G;
            }
        }
    }
}

// =====================================================================
// Scan phase 1: per (b, chunk) carry (A,B), float2-vectorized
// =====================================================================
__global__ __launch_bounds__(256) void scan_phase1()
{
    int c = blockIdx.x, b = blockIdx.z, t = threadIdx.x;
    long long base2 = ((long long)(b*SS + c*CLEN)*HH) >> 1;
    const float2* ap = (const float2*)g_a + base2 + t;
    const float2* bp = (const float2*)g_b + base2 + t;
    float Ax = 1.f, Ay = 1.f, Bx = 0.f, By = 0.f;
    #pragma unroll 8
    for (int s = 0; s < CLEN; ++s) {
        float2 a = ap[(long long)s*(HH/2)];
        float2 v = bp[(long long)s*(HH/2)];
        Bx = a.x*Bx + v.x;  By = a.y*By + v.y;
        Ax *= a.x;          Ay *= a.y;
    }
    int ci = (b*CHUNKS + c)*HH + 2*t;
    *(float2*)&g_Ac[ci] = make_float2(Ax, Ay);
    *(float2*)&g_Bc[ci] = make_float2(Bx, By);
}

// =====================================================================
// Scan phase 2: sequential over chunks per channel
// =====================================================================
__global__ __launch_bounds__(256) void scan_phase2()
{
    int t = blockIdx.x*256 + threadIdx.x;     // 0..4095
    int b = t >> 9, hh = t & 511;
    float run = 0.f;
    for (int c = 0; c < CHUNKS; ++c) {
        int ci = (b*CHUNKS + c)*HH + hh;
        g_H0[ci] = run;
        run = g_Ac[ci]*run + g_Bc[ci];
    }
}

// =====================================================================
// Scan phase 3: recurrence within chunk -> bf16 hi/lo h; exact fp32 h_n
// =====================================================================
__global__ __launch_bounds__(256) void scan_phase3()
{
    int c = blockIdx.x, b = blockIdx.z, t = threadIdx.x;
    long long base2 = ((long long)(b*SS + c*CLEN)*HH) >> 1;
    const float2* ap = (const float2*)g_a + base2 + t;
    const float2* bp = (const float2*)g_b + base2 + t;
    unsigned* hhp = (unsigned*)g_hh + base2 + t;
    unsigned* hlp = (unsigned*)g_hl + base2 + t;
    int ci = (b*CHUNKS + c)*HH + 2*t;
    float h0 = g_H0[ci], h1 = g_H0[ci+1];
    #pragma unroll 8
    for (int s = 0; s < CLEN; ++s) {
        float2 a = ap[(long long)s*(HH/2)];
        float2 v = bp[(long long)s*(HH/2)];
        h0 = a.x*h0 + v.x;
        h1 = a.y*h1 + v.y;
        __nv_bfloat16 h0h = __float2bfloat16(h0), h1h = __float2bfloat16(h1);
        __nv_bfloat16 h0l = __float2bfloat16(h0 - __bfloat162float(h0h));
        __nv_bfloat16 h1l = __float2bfloat16(h1 - __bfloat162float(h1h));
        __nv_bfloat162 ph = __halves2bfloat162(h0h, h1h);
        __nv_bfloat162 pl = __halves2bfloat162(h0l, h1l);
        hhp[(long long)s*(HH/2)] = *(unsigned*)&ph;
        hlp[(long long)s*(HH/2)] = *(unsigned*)&pl;
    }
    if (c == CHUNKS-1) {
        g_hn[b*HH + 2*t]   = h0;
        g_hn[b*HH + 2*t+1] = h1;
    }
}

// =====================================================================
// GEMM2: out = h @ W_out^T (bf16-split HMMA + ldmatrix + dbl-buffer)
// grid = (8, 512); n0 = bx*64
// =====================================================================
__global__ __launch_bounds__(256, 2) void gemm2_mma(float* __restrict__ out)
{
    __shared__ __align__(16) unsigned short Ah[2][128][SPAD], Al[2][128][SPAD];
    __shared__ __align__(16) unsigned short Bh[2][64][SPAD],  Bl[2][64][SPAD];

    const int tid = threadIdx.x;
    const int m0  = blockIdx.y * 128;
    const int n0  = blockIdx.x * 64;

    const int lane = tid & 31;
    const int wid  = tid >> 5;
    const int wm   = wid & 3;
    const int wn   = wid >> 2;
    const int g    = lane >> 2;
    const int tg   = lane & 3;

    const int m4    = lane >> 3;
    const int arowf = (lane & 7) + (m4 & 1)*8;
    const int akcol = (m4 >> 1)*8;
    const int bcolf = (lane & 7) + (m4 >> 1)*8;
    const int bkcol = (m4 & 1)*8;

    const int arow = tid >> 1, ahalf = tid & 1;
    const int brow = (tid & 127) >> 1, bhalf = tid & 1;

    const uint4* AHp = (const uint4*)g_hh;
    const uint4* ALp = (const uint4*)g_hl;
    const uint4* WH  = (const uint4*)g_wout_h;
    const uint4* WL  = (const uint4*)g_wout_l;

    uint4 pah, pal, pbh, pbl;
    auto ldg = [&](int kt) {
        long long ai = ((long long)(m0 + arow)*HH + kt*BK + ahalf*8) >> 3;
        pah = AHp[ai];  pal = ALp[ai];
        if (tid < 128) {
            long long bi = ((long long)(n0 + brow)*HH + kt*BK + bhalf*8) >> 3;
            pbh = WH[bi];  pbl = WL[bi];
        }
    };
    auto stg = [&](int buf) {
        *(uint4*)&Ah[buf][arow][ahalf*8] = pah;
        *(uint4*)&Al[buf][arow][ahalf*8] = pal;
        if (tid < 128) {
            *(uint4*)&Bh[buf][brow][bhalf*8] = pbh;
            *(uint4*)&Bl[buf][brow][bhalf*8] = pbl;
        }
    };

    float acc[2][4][4];
    #pragma unroll
    for (int i = 0; i < 2; ++i)
        #pragma unroll
        for (int j = 0; j < 4; ++j)
            #pragma unroll
            for (int q = 0; q < 4; ++q) acc[i][j][q] = 0.f;

    ldg(0); stg(0);
    __syncthreads();

    const int KT = HH / BK;   // 32
    #pragma unroll 2
    for (int kt = 0; kt < KT; ++kt) {
        const int buf = kt & 1;
        if (kt + 1 < KT) ldg(kt + 1);

        unsigned ah[2][4], al[2][4], bh[4][2], bl[4][2], t[4];
        #pragma unroll
        for (int fm = 0; fm < 2; ++fm) {
            ldsm4(ah[fm], &Ah[buf][wm*32 + fm*16 + arowf][akcol]);
            ldsm4(al[fm], &Al[buf][wm*32 + fm*16 + arowf][akcol]);
        }
        #pragma unroll
        for (int pr = 0; pr < 2; ++pr) {
            ldsm4(t, &Bh[buf][wn*32 + pr*16 + bcolf][bkcol]);
            bh[2*pr][0]=t[0]; bh[2*pr][1]=t[1]; bh[2*pr+1][0]=t[2]; bh[2*pr+1][1]=t[3];
            ldsm4(t, &Bl[buf][wn*32 + pr*16 + bcolf][bkcol]);
            bl[2*pr][0]=t[0]; bl[2*pr][1]=t[1]; bl[2*pr+1][0]=t[2]; bl[2*pr+1][1]=t[3];
        }

        #pragma unroll
        for (int fm = 0; fm < 2; ++fm)
            #pragma unroll
            for (int nf = 0; nf < 4; ++nf) {
                float* d = acc[fm][nf];
                mma_bf16(d[0],d[1],d[2],d[3], ah[fm][0],ah[fm][1],ah[fm][2],ah[fm][3], bh[nf][0],bh[nf][1]);
                mma_bf16(d[0],d[1],d[2],d[3], ah[fm][0],ah[fm][1],ah[fm][2],ah[fm][3], bl[nf][0],bl[nf][1]);
                mma_bf16(d[0],d[1],d[2],d[3], al[fm][0],al[fm][1],al[fm][2],al[fm][3], bh[nf][0],bh[nf][1]);
            }

        if (kt + 1 < KT) stg(buf ^ 1);
        __syncthreads();
    }

    #pragma unroll
    for (int fm = 0; fm < 2; ++fm) {
        #pragma unroll
        for (int nf = 0; nf < 4; ++nf) {
            int cc = n0 + wn*32 + nf*8 + 2*tg;
            int r0 = m0 + wm*32 + fm*16 + g;
            float2 v0 = make_float2(acc[fm][nf][0], acc[fm][nf][1]);
            float2 v1 = make_float2(acc[fm][nf][2], acc[fm][nf][3]);
            *(float2*)&out[(long long)r0*OO + cc]       = v0;
            *(float2*)&out[(long long)(r0+8)*OO + cc]   = v1;
        }
    }
}

// =====================================================================
// h_n copy: exact fp32 last-step h -> tail of output buffer
// =====================================================================
__global__ void copy_hn(float* __restrict__ out)
{
    int t = blockIdx.x*256 + threadIdx.x;     // 0..4095
    out[(long long)MM*OO + t] = g_hn[t];
}

// =====================================================================
// launch
// =====================================================================
extern "C" void kernel_launch(void* const* d_in, const int* in_sizes, int n_in,
                              void* d_out, int out_size)
{
    const float* x    = (const float*)d_in[0];
    // d_in[1] = is_init : unused by the reference (all false)
    const float* Whg  = (const float*)d_in[2];
    const float* Wout = (const float*)d_in[3];
    float* out = (float*)d_out;

    split_x   <<<(MM*DD/4)/256,   256>>>((const float4*)x);
    split_whg <<<(2*HH*DD/4)/256, 256>>>((const float4*)Whg);
    split_wout<<<(OO*HH/4)/256,   256>>>((const float4*)Wout);

    gemm1_mma<<<dim3(16, MM/128), 256>>>();
    scan_phase1<<<dim3(CHUNKS, 1, BB), 256>>>();
    scan_phase2<<<16, 256>>>();
    scan_phase3<<<dim3(CHUNKS, 1, BB), 256>>>();
    gemm2_mma<<<dim3(8, MM/128), 256>>>(out);

    long long need = (long long)MM*OO + (long long)BB*HH;
    if ((long long)out_size >= need)
        copy_hn<<<16, 256>>>(out);
}